// round 4
// baseline (speedup 1.0000x reference)
#include <cuda_runtime.h>
#include <cstdint>

// Problem: B=8, C=256, H=W=64, K=3, pad=1, stride=1
// out_flat[f] = keyflat[f] * qv[f/9], f in [0, 9*4096) per (b,c) slice
//   keyflat[f] = padded key tile at (l>>6 + kk/3, (l&63) + kk%3), kk=f>>12, l=f&4095
//   qv[l']     = padded query tile read at fq = 9*l'+4
#define HW    64
#define PITCH 66
#define TILEW (PITCH * PITCH)   // 4356 words (divisible by 4)
#define SEG   (TILEW / 4)       // 1089 words per plane
#define LSZ   4096
#define F4PC  9216

// Plane-split physical address: word w -> plane (w&3), index (w>>2).
// Makes lane-stride-4-word accesses conflict-free.
__device__ __forceinline__ int paddr(int w) {
    return (w & 3) * SEG + (w >> 2);
}

__global__ void __launch_bounds__(256, 6)
appearance_kernel(const float* __restrict__ key,
                  const float* __restrict__ query,
                  float* __restrict__ out) {
    __shared__ float pad[TILEW];     // 17424 B, plane-split; query then key
    __shared__ float qv[LSZ + 1];    // 16388 B

    const int tid = threadIdx.x;
    const int bc  = blockIdx.x;      // 0..2047

    const float4* kb4 = (const float4*)(key   + (size_t)bc * LSZ);
    const float4* qb4 = (const float4*)(query + (size_t)bc * LSZ);

    // ---- phase 1: zero all 260 border cells + scatter query into planes ----
    for (int i = tid; i < 260; i += 256) {   // blockDim=256 < 260: loop!
        int w;
        if      (i < 66)  w = i;                          // top row
        else if (i < 132) w = 65 * PITCH + (i - 66);      // bottom row
        else if (i < 196) w = (i - 131) * PITCH;          // left col, rows 1..64
        else              w = (i - 195) * PITCH + 65;     // right col, rows 1..64
        pad[paddr(w)] = 0.0f;
    }
    #pragma unroll
    for (int k = 0; k < 4; k++) {
        float4 v = qb4[tid + k * 256];
        int l  = (tid + k * 256) << 2;
        int w0 = ((l >> 6) + 1) * PITCH + (l & 63) + 1;
        pad[paddr(w0 + 0)] = v.x;
        pad[paddr(w0 + 1)] = v.y;
        pad[paddr(w0 + 2)] = v.z;
        pad[paddr(w0 + 3)] = v.w;
    }
    __syncthreads();

    // ---- phase 2: qv[l'] = query patch at fq = 9*l' + 4 ----
    #pragma unroll
    for (int k = 0; k < 16; k++) {
        int i  = tid + k * 256;
        int fq = 9 * i + 4;
        int kk = fq >> 12;
        int lq = fq & 4095;
        int w  = ((lq >> 6) + kk / 3) * PITCH + (lq & 63) + kk % 3;
        qv[i] = pad[paddr(w)];
    }
    if (tid == 0) qv[LSZ] = 0.0f;
    __syncthreads();

    // ---- phase 3: scatter key into planes (borders stay zero) ----
    #pragma unroll
    for (int k = 0; k < 4; k++) {
        float4 v = kb4[tid + k * 256];
        int l  = (tid + k * 256) << 2;
        int w0 = ((l >> 6) + 1) * PITCH + (l & 63) + 1;
        pad[paddr(w0 + 0)] = v.x;
        pad[paddr(w0 + 1)] = v.y;
        pad[paddr(w0 + 2)] = v.z;
        pad[paddr(w0 + 3)] = v.w;
    }
    __syncthreads();

    // ---- main loop: 36 float4 outputs per thread ----
    float4* out4 = (float4*)out + (size_t)bc * F4PC;
    const int l0  = tid << 2;
    const int row = l0 >> 6;
    const int col = l0 & 63;

    #pragma unroll
    for (int kk = 0; kk < 9; kk++) {
        const int dr = kk / 3, dc = kk % 3;
        #pragma unroll
        for (int it = 0; it < 4; it++) {
            const int b = (row + it * 16 + dr) * PITCH + col + dc;
            const float k0 = pad[paddr(b + 0)];
            const float k1 = pad[paddr(b + 1)];
            const float k2 = pad[paddr(b + 2)];
            const float k3 = pad[paddr(b + 3)];

            const int f = kk * LSZ + it * 1024 + l0;
            const unsigned lp0 = (unsigned)f / 9u;   // mul-hi
            const int rem = f - (int)lp0 * 9;        // 0..8
            const float q0 = qv[lp0];
            const float q1 = qv[lp0 + 1];

            float4 o;
            o.x = k0 * q0;
            o.y = k1 * (rem >= 8 ? q1 : q0);
            o.z = k2 * (rem >= 7 ? q1 : q0);
            o.w = k3 * (rem >= 6 ? q1 : q0);
            out4[kk * 1024 + it * 256 + tid] = o;
        }
    }
}

extern "C" void kernel_launch(void* const* d_in, const int* in_sizes, int n_in,
                              void* d_out, int out_size) {
    const float* key   = (const float*)d_in[0];
    const float* query = (const float*)d_in[1];
    float* out = (float*)d_out;

    appearance_kernel<<<2048, 256>>>(key, query, out);
}

// round 5
// speedup vs baseline: 1.1914x; 1.1914x over previous
#include <cuda_runtime.h>
#include <cstdint>

// Problem: B=8, C=256, H=W=64, K=3, pad=1, stride=1
// out_flat[f] = keyflat[f] * qv[f/9], f in [0, 9*4096) per (b,c) slice
//   keyflat[f] = padded key tile at (l>>6 + kk/3, (l&63) + kk%3), kk=f>>12, l=f&4095
//   qv[l']     = padded query tile read at fq = 9*l'+4
#define HW    64
#define PITCH 68                // 66 rows x 68 cols; 68%4==0 -> aligned vector LDS
#define ROWS  66
#define TILEW (ROWS * PITCH)    // 4488 words
#define LSZ   4096
#define F4PC  9216

__global__ void __launch_bounds__(256)
appearance_kernel(const float* __restrict__ key,
                  const float* __restrict__ query,
                  float* __restrict__ out) {
    __shared__ alignas(16) float pad[TILEW];   // 17952 B, query then key
    __shared__ alignas(16) float qv[LSZ + 1];  // 16388 B

    const int tid = threadIdx.x;
    const int bc  = blockIdx.x;      // 0..2047

    const float4* kb4 = (const float4*)(key   + (size_t)bc * LSZ);
    const float4* qb4 = (const float4*)(query + (size_t)bc * LSZ);

    // ---- zero full padded tile (borders must be 0) ----
    for (int i = tid; i < TILEW; i += 256) pad[i] = 0.0f;
    __syncthreads();

    // ---- phase 1: query -> padded tile (image pixel (r,c) at (r+1, c+1)) ----
    #pragma unroll
    for (int k = 0; k < 4; k++) {
        float4 v = qb4[tid + k * 256];
        int l = (tid + k * 256) << 2;
        float* p = &pad[((l >> 6) + 1) * PITCH + (l & 63) + 1];
        p[0] = v.x; p[1] = v.y; p[2] = v.z; p[3] = v.w;
    }
    __syncthreads();

    // ---- phase 2: qv[l'] = query patch at fq = 9*l' + 4 (no bounds checks) ----
    #pragma unroll
    for (int k = 0; k < 16; k++) {
        int i  = tid + k * 256;
        int fq = 9 * i + 4;
        int kkq = fq >> 12;
        int lq  = fq & 4095;
        qv[i] = pad[((lq >> 6) + kkq / 3) * PITCH + (lq & 63) + kkq % 3];
    }
    if (tid == 0) qv[LSZ] = 0.0f;
    __syncthreads();

    // ---- phase 3: key -> padded tile (borders stay zero) ----
    #pragma unroll
    for (int k = 0; k < 4; k++) {
        float4 v = kb4[tid + k * 256];
        int l = (tid + k * 256) << 2;
        float* p = &pad[((l >> 6) + 1) * PITCH + (l & 63) + 1];
        p[0] = v.x; p[1] = v.y; p[2] = v.z; p[3] = v.w;
    }
    __syncthreads();

    // ---- main loop: dr-major; one float4+float2 window serves dc=0,1,2 ----
    float4* out4 = (float4*)out + (size_t)bc * F4PC;
    const int l0  = tid << 2;        // multiple of 4
    const int row = l0 >> 6;
    const int col = l0 & 63;         // multiple of 4 -> 16B-aligned window

    #pragma unroll
    for (int it = 0; it < 4; it++) {
        #pragma unroll
        for (int dr = 0; dr < 3; dr++) {
            const float* wp = &pad[(row + it * 16 + dr) * PITCH + col];
            const float4 a = *(const float4*)wp;         // w0..w3
            const float2 b = *(const float2*)(wp + 4);   // w4,w5
            const float w0 = a.x, w1 = a.y, w2 = a.z, w3 = a.w, w4 = b.x, w5 = b.y;

            #pragma unroll
            for (int dc = 0; dc < 3; dc++) {
                const int kk = 3 * dr + dc;
                const int f  = kk * LSZ + it * 1024 + l0;
                const unsigned lp0 = (unsigned)f / 9u;   // mul-hi
                const int rem = f - (int)lp0 * 9;        // 0..8
                const float q0 = qv[lp0];
                const float q1 = qv[lp0 + 1];

                float4 o;
                o.x = (dc == 0 ? w0 : dc == 1 ? w1 : w2) * q0;
                o.y = (dc == 0 ? w1 : dc == 1 ? w2 : w3) * (rem >= 8 ? q1 : q0);
                o.z = (dc == 0 ? w2 : dc == 1 ? w3 : w4) * (rem >= 7 ? q1 : q0);
                o.w = (dc == 0 ? w3 : dc == 1 ? w4 : w5) * (rem >= 6 ? q1 : q0);
                out4[kk * 1024 + it * 256 + tid] = o;
            }
        }
    }
}

extern "C" void kernel_launch(void* const* d_in, const int* in_sizes, int n_in,
                              void* d_out, int out_size) {
    const float* key   = (const float*)d_in[0];
    const float* query = (const float*)d_in[1];
    float* out = (float*)d_out;

    appearance_kernel<<<2048, 256>>>(key, query, out);
}